// round 16
// baseline (speedup 1.0000x reference)
#include <cuda_runtime.h>
#include <cuda_bf16.h>
#include <math.h>
#include <stdint.h>

#define Bq   2
#define Sq   2048
#define Dm   512
#define Hh   8
#define DKq  64
#define Lq   4
#define DFFq 2048
#define Vv   32000
#define ROWS (Bq*Sq)   // 4096

// ---------------- scratch (device globals; no runtime alloc) ----------------
__device__ float g_x[ROWS*Dm];

__device__ __nv_bfloat16 g_aHi[ROWS*Dm];      // ln / attn outputs (<=512 wide)
__device__ __nv_bfloat16 g_aLo[ROWS*Dm];
__device__ __nv_bfloat16 g_bHi[ROWS*DFFq];    // qkv split (1536) / FF intermediate (2048)
__device__ __nv_bfloat16 g_bLo[ROWS*DFFq];

__device__ __nv_bfloat16 g_qkvT_hi[Lq*3*Dm*Dm], g_qkvT_lo[Lq*3*Dm*Dm];
__device__ __nv_bfloat16 g_woT_hi [Lq*Dm*Dm],   g_woT_lo [Lq*Dm*Dm];
__device__ __nv_bfloat16 g_w1T_hi [Lq*DFFq*Dm], g_w1T_lo [Lq*DFFq*Dm];
__device__ __nv_bfloat16 g_w2T_hi [Lq*Dm*DFFq], g_w2T_lo [Lq*Dm*DFFq];
__device__ __nv_bfloat16 g_hdT_hi [(long long)Vv*Dm], g_hdT_lo[(long long)Vv*Dm];

// ---------------- helpers ----------------
__device__ __forceinline__ uint32_t smem_u32(const void* p) {
    uint32_t a;
    asm("{ .reg .u64 t; cvta.to.shared.u64 t, %1; cvt.u32.u64 %0, t; }" : "=r"(a) : "l"(p));
    return a;
}
__device__ __forceinline__ uint32_t swz(uint32_t off)    { return off ^ ((off >> 3) & 0x30u); }       // 64B rows
__device__ __forceinline__ uint32_t swz128(uint32_t off) { return off ^ (((off >> 7) & 7u) << 4); }   // 128B rows

__device__ __forceinline__ void cpa16(uint32_t dst, const void* src) {
    asm volatile("cp.async.cg.shared.global [%0], [%1], 16;" :: "r"(dst), "l"(src));
}
#define CP_COMMIT() asm volatile("cp.async.commit_group;" ::: "memory")
#define CP_WAIT1()  asm volatile("cp.async.wait_group 1;" ::: "memory")
#define CP_WAIT0()  asm volatile("cp.async.wait_group 0;" ::: "memory")

#define LDSM4(r, a) \
    asm volatile("ldmatrix.sync.aligned.m8n8.x4.shared.b16 {%0,%1,%2,%3}, [%4];" \
        : "=r"((r)[0]), "=r"((r)[1]), "=r"((r)[2]), "=r"((r)[3]) : "r"(a))
#define LDSM4T(r, a) \
    asm volatile("ldmatrix.sync.aligned.m8n8.x4.trans.shared.b16 {%0,%1,%2,%3}, [%4];" \
        : "=r"((r)[0]), "=r"((r)[1]), "=r"((r)[2]), "=r"((r)[3]) : "r"(a))

#define MMA(d, a, b0_, b1_) \
    asm volatile("mma.sync.aligned.m16n8k16.row.col.f32.bf16.bf16.f32 " \
        "{%0,%1,%2,%3}, {%4,%5,%6,%7}, {%8,%9}, {%0,%1,%2,%3};" \
        : "+f"((d)[0]), "+f"((d)[1]), "+f"((d)[2]), "+f"((d)[3]) \
        : "r"((a)[0]), "r"((a)[1]), "r"((a)[2]), "r"((a)[3]), "r"(b0_), "r"(b1_))

__device__ __forceinline__ uint32_t pack_hi(float a, float b) {
    return ((uint32_t)__bfloat16_as_ushort(__float2bfloat16(b)) << 16)
         |  (uint32_t)__bfloat16_as_ushort(__float2bfloat16(a));
}
__device__ __forceinline__ uint32_t pack_lo(float a, float b) {
    float ra = a - __bfloat162float(__float2bfloat16(a));
    float rb = b - __bfloat162float(__float2bfloat16(b));
    return ((uint32_t)__bfloat16_as_ushort(__float2bfloat16(rb)) << 16)
         |  (uint32_t)__bfloat16_as_ushort(__float2bfloat16(ra));
}

// ---------------------------------------------------------------------------
// Embedding
// ---------------------------------------------------------------------------
__global__ __launch_bounds__(128) void embed_kernel(
    const int* __restrict__ tokens, const float* __restrict__ emb,
    const float* __restrict__ pe, float* __restrict__ x)
{
    int r = blockIdx.x, t = threadIdx.x;
    int tok = tokens[r];
    int s = r & (Sq - 1);
    const float sc = 22.62741699796952f;
    float4 e = *(const float4*)(emb + (long long)tok * Dm + t * 4);
    float4 p = *(const float4*)(pe + (long long)s * Dm + t * 4);
    float4 o;
    o.x = e.x * sc + p.x; o.y = e.y * sc + p.y;
    o.z = e.z * sc + p.z; o.w = e.w * sc + p.w;
    *(float4*)(x + (long long)r * Dm + t * 4) = o;
}

// ---------------------------------------------------------------------------
// LayerNorm -> bf16 hi/lo
// ---------------------------------------------------------------------------
__global__ __launch_bounds__(128) void ln_kernel(
    const float* __restrict__ x, const float* __restrict__ sc,
    const float* __restrict__ bi,
    __nv_bfloat16* __restrict__ hi, __nv_bfloat16* __restrict__ lo)
{
    int r = blockIdx.x, t = threadIdx.x;
    float4 v = *(const float4*)(x + (long long)r * Dm + t * 4);
    float sum = v.x + v.y + v.z + v.w;
    float sq  = v.x*v.x + v.y*v.y + v.z*v.z + v.w*v.w;
    #pragma unroll
    for (int o = 16; o > 0; o >>= 1) {
        sum += __shfl_xor_sync(0xffffffffu, sum, o);
        sq  += __shfl_xor_sync(0xffffffffu, sq,  o);
    }
    __shared__ float wsum[4], wsq[4];
    if ((t & 31) == 0) { wsum[t >> 5] = sum; wsq[t >> 5] = sq; }
    __syncthreads();
    float tot   = wsum[0] + wsum[1] + wsum[2] + wsum[3];
    float totsq = wsq[0]  + wsq[1]  + wsq[2]  + wsq[3];
    float mu  = tot * (1.0f / Dm);
    float var = totsq * (1.0f / Dm) - mu * mu;
    float rs  = rsqrtf(var + 1e-5f);
    float4 s4 = *(const float4*)(sc + t * 4);
    float4 b4 = *(const float4*)(bi + t * 4);
    float o0 = (v.x - mu) * rs * s4.x + b4.x;
    float o1 = (v.y - mu) * rs * s4.y + b4.y;
    float o2 = (v.z - mu) * rs * s4.z + b4.z;
    float o3 = (v.w - mu) * rs * s4.w + b4.w;
    uint2 ph, pl;
    ph.x = pack_hi(o0, o1); ph.y = pack_hi(o2, o3);
    pl.x = pack_lo(o0, o1); pl.y = pack_lo(o2, o3);
    *(uint2*)&hi[(long long)r * Dm + t * 4] = ph;
    *(uint2*)&lo[(long long)r * Dm + t * 4] = pl;
}

// ---------------------------------------------------------------------------
// Weight transpose + split: W [K,N] fp32 -> hiT/loT [N,K] bf16
// ---------------------------------------------------------------------------
__global__ __launch_bounds__(256) void wsplit_kernel(
    const float* __restrict__ W, __nv_bfloat16* __restrict__ hiT,
    __nv_bfloat16* __restrict__ loT, int K, int N)
{
    __shared__ float t[32][33];
    int nb = blockIdx.x * 32, kb = blockIdx.y * 32;
    int tx = threadIdx.x & 31, ty = threadIdx.x >> 5;
    #pragma unroll
    for (int i = 0; i < 32; i += 8)
        t[ty + i][tx] = W[(long long)(kb + ty + i) * N + nb + tx];
    __syncthreads();
    #pragma unroll
    for (int i = 0; i < 32; i += 8) {
        int r = ty + i;
        float v = t[tx][r];
        __nv_bfloat16 h = __float2bfloat16(v);
        __nv_bfloat16 l = __float2bfloat16(v - __bfloat162float(h));
        long long o = (long long)(nb + r) * K + kb + tx;
        hiT[o] = h; loT[o] = l;
    }
}

// ---------------------------------------------------------------------------
// mma.sync bf16 GEMM, hi/lo split (3 MMAs per k16).
// 512 threads, 16 warps (4x4), CTA tile 128x128, warp tile 32x32.
// mode 0: fp32 + bias. mode 1: fp32 + bias + res. mode 2: GELU -> hi/lo.
// mode 3: bias -> hi/lo (QKV path).
// ---------------------------------------------------------------------------
__global__ __launch_bounds__(512, 1) void gemm_mma(
    const __nv_bfloat16* __restrict__ Ahi, const __nv_bfloat16* __restrict__ Alo,
    const __nv_bfloat16* __restrict__ Bhi, const __nv_bfloat16* __restrict__ Blo,
    const float* __restrict__ bias, const float* __restrict__ res,
    float* __restrict__ C, __nv_bfloat16* __restrict__ CHi,
    __nv_bfloat16* __restrict__ CLo, int N, int K, int mode)
{
    extern __shared__ __align__(1024) char smem[];
    uint32_t smemBase = smem_u32(smem);
    int tid = threadIdx.x, lane = tid & 31, wid = tid >> 5;
    int wm = wid >> 2, wn = wid & 3;
    long long rowBase = (long long)blockIdx.y * 128;
    long long colBase = (long long)blockIdx.x * 128;

    const __nv_bfloat16* a0g = Ahi + rowBase * K;
    const __nv_bfloat16* a1g = Alo + rowBase * K;
    const __nv_bfloat16* b0g = Bhi + colBase * K;
    const __nv_bfloat16* b1g = Blo + colBase * K;

    int ld_row = tid >> 2, ld_c16 = tid & 3;   // 512 thr: rows 0..127, 4 sectors
    uint32_t offA = swz((uint32_t)(ld_row * 64 + ld_c16 * 16));

    auto load_stage = [&](int stg, int kc) {
        uint32_t sb = smemBase + (uint32_t)stg * 32768u;
        long long g0 = (long long)ld_row * K + kc + ld_c16 * 8;
        cpa16(sb + offA,          a0g + g0);
        cpa16(sb + 8192 + offA,   a1g + g0);
        cpa16(sb + 16384 + offA,  b0g + g0);
        cpa16(sb + 24576 + offA,  b1g + g0);
        CP_COMMIT();
    };

    int NC = K >> 5;
    load_stage(0, 0);
    if (NC > 1) load_stage(1, 32);

    float acc[2][4][4] = {};
    int rl = lane & 15, cl = lane >> 4;

    for (int c = 0; c < NC; c++) {
        if (c + 1 < NC) { CP_WAIT1(); } else { CP_WAIT0(); }
        __syncthreads();
        uint32_t sb = smemBase + (uint32_t)(c % 3) * 32768u;
        #pragma unroll
        for (int hk = 0; hk < 2; hk++) {
            uint32_t ah[2][4], al[2][4], bh[2][4], bl[2][4];
            #pragma unroll
            for (int mt = 0; mt < 2; mt++) {
                uint32_t off = swz((uint32_t)((wm * 32 + mt * 16 + rl) * 64 + (hk * 2 + cl) * 16));
                LDSM4(ah[mt], sb + off);
                LDSM4(al[mt], sb + 8192 + off);
            }
            #pragma unroll
            for (int np = 0; np < 2; np++) {
                uint32_t off = swz((uint32_t)((wn * 32 + np * 16 + rl) * 64 + (hk * 2 + cl) * 16));
                LDSM4(bh[np], sb + 16384 + off);
                LDSM4(bl[np], sb + 24576 + off);
            }
            #pragma unroll
            for (int mt = 0; mt < 2; mt++)
                #pragma unroll
                for (int nt = 0; nt < 4; nt++) {
                    int np = nt >> 1, s = nt & 1;
                    MMA(acc[mt][nt], ah[mt], bh[np][s], bh[np][2 + s]);
                    MMA(acc[mt][nt], ah[mt], bl[np][s], bl[np][2 + s]);
                    MMA(acc[mt][nt], al[mt], bh[np][s], bh[np][2 + s]);
                }
        }
        __syncthreads();
        if (c + 2 < NC) load_stage((c + 2) % 3, (c + 2) * 32);
    }

    const float kk = 0.7071067811865475f;
    #pragma unroll
    for (int mt = 0; mt < 2; mt++) {
        #pragma unroll
        for (int nt = 0; nt < 4; nt++) {
            long long row = rowBase + wm * 32 + mt * 16 + (lane >> 2);
            long long col = colBase + wn * 32 + nt * 8 + (lane & 3) * 2;
            float bx = bias[col], by = bias[col + 1];
            #pragma unroll
            for (int hh = 0; hh < 2; hh++) {
                long long rr = row + hh * 8;
                float v0 = acc[mt][nt][hh * 2 + 0] + bx;
                float v1 = acc[mt][nt][hh * 2 + 1] + by;
                if (mode == 1) {
                    float2 r2 = *(const float2*)(res + rr * N + col);
                    v0 += r2.x; v1 += r2.y;
                    float2 o2; o2.x = v0; o2.y = v1;
                    *(float2*)(C + rr * N + col) = o2;
                } else if (mode == 2) {
                    v0 = 0.5f * v0 * (1.0f + erff(v0 * kk));
                    v1 = 0.5f * v1 * (1.0f + erff(v1 * kk));
                    *(uint32_t*)&CHi[rr * N + col] = pack_hi(v0, v1);
                    *(uint32_t*)&CLo[rr * N + col] = pack_lo(v0, v1);
                } else if (mode == 3) {
                    *(uint32_t*)&CHi[rr * N + col] = pack_hi(v0, v1);
                    *(uint32_t*)&CLo[rr * N + col] = pack_lo(v0, v1);
                } else {
                    float2 o2; o2.x = v0; o2.y = v1;
                    *(float2*)(C + rr * N + col) = o2;
                }
            }
        }
    }
}

// ---------------------------------------------------------------------------
// Tensor-core causal flash attention, hi/lo split (unchanged from R9).
// ---------------------------------------------------------------------------
__global__ __launch_bounds__(256, 1) void attn_mma(
    const __nv_bfloat16* __restrict__ gHi, const __nv_bfloat16* __restrict__ gLo,
    __nv_bfloat16* __restrict__ outHi, __nv_bfloat16* __restrict__ outLo)
{
    extern __shared__ __align__(1024) char smem[];
    uint32_t sb = smem_u32(smem);
    const uint32_t sQh = sb, sQl = sb + 16384;
    int tid = threadIdx.x, lane = tid & 31, w = tid >> 5;
    int qBlock = (int)gridDim.x - 1 - (int)blockIdx.x;
    int qBase = qBlock * 128;
    int h = blockIdx.y, bb = blockIdx.z;
    long long rowOff = (long long)bb * Sq;

    #pragma unroll
    for (int i = 0; i < 4; i++) {
        int idx = i * 256 + tid;
        int r = idx >> 3, sg = idx & 7;
        long long g = (rowOff + qBase + r) * 1536 + h * 64 + sg * 8;
        uint32_t o = swz128((uint32_t)(r * 128 + sg * 16));
        cpa16(sQh + o, gHi + g);
        cpa16(sQl + o, gLo + g);
    }
    CP_COMMIT();

    int numT = qBase / 64 + 2;
    auto loadKV = [&](int s, int kb) {
        uint32_t base = sb + 32768u + (uint32_t)s * 32768u;
        #pragma unroll
        for (int i = 0; i < 2; i++) {
            int idx = i * 256 + tid;
            int r = idx >> 3, sg = idx & 7;
            uint32_t o = swz128((uint32_t)(r * 128 + sg * 16));
            long long gk = (rowOff + kb + r) * 1536 + 512 + h * 64 + sg * 8;
            cpa16(base + o,          gHi + gk);
            cpa16(base + 8192 + o,   gLo + gk);
            cpa16(base + 16384 + o,  gHi + gk + 512);
            cpa16(base + 24576 + o,  gLo + gk + 512);
        }
        CP_COMMIT();
    };
    loadKV(0, 0);
    if (numT > 1) loadKV(1, 64);

    if (numT > 1) { CP_WAIT1(); } else { CP_WAIT0(); }
    __syncthreads();

    int rl = lane & 15, cl = lane >> 4;
    uint32_t qh[4][4], ql[4][4];
    #pragma unroll
    for (int k16 = 0; k16 < 4; k16++) {
        uint32_t o = swz128((uint32_t)((w * 16 + rl) * 128 + (k16 * 2 + cl) * 16));
        LDSM4(qh[k16], sQh + o);
        LDSM4(ql[k16], sQl + o);
    }

    float oacc[8][4] = {};
    float m0 = -1e30f, m1 = -1e30f, l0 = 0.f, l1 = 0.f;
    int row0 = qBase + w * 16 + (lane >> 2);
    int row1 = row0 + 8;

    for (int t = 0; t < numT; t++) {
        if (t + 1 < numT) { CP_WAIT1(); } else { CP_WAIT0(); }
        __syncthreads();
        int kb = t * 64;
        if (kb <= qBase + w * 16 + 15) {
            uint32_t base = sb + 32768u + (uint32_t)(t & 1) * 32768u;
            float sacc[8][4] = {};
            #pragma unroll
            for (int k16 = 0; k16 < 4; k16++) {
                uint32_t bKh[4][4], bKl[4][4];
                #pragma unroll
                for (int np = 0; np < 4; np++) {
                    uint32_t o = swz128((uint32_t)((np * 16 + rl) * 128 + (k16 * 2 + cl) * 16));
                    LDSM4(bKh[np], base + o);
                    LDSM4(bKl[np], base + 8192 + o);
                }
                #pragma unroll
                for (int nt = 0; nt < 8; nt++) {
                    int np = nt >> 1, s = nt & 1;
                    MMA(sacc[nt], qh[k16], bKh[np][s], bKh[np][2 + s]);
                    MMA(sacc[nt], qh[k16], bKl[np][s], bKl[np][2 + s]);
                    MMA(sacc[nt], ql[k16], bKh[np][s], bKh[np][2 + s]);
                }
            }
            float mx0 = -1e30f, mx1 = -1e30f;
            #pragma unroll
            for (int nt = 0; nt < 8; nt++) {
                #pragma unroll
                for (int j = 0; j < 4; j++) {
                    int col = kb + nt * 8 + (lane & 3) * 2 + (j & 1);
                    int rw = (j < 2) ? row0 : row1;
                    float v = sacc[nt][j] * 0.125f;
                    if (col > rw) v = -1e30f;
                    sacc[nt][j] = v;
                    if (j < 2) mx0 = fmaxf(mx0, v); else mx1 = fmaxf(mx1, v);
                }
            }
            mx0 = fmaxf(mx0, __shfl_xor_sync(0xffffffffu, mx0, 1));
            mx0 = fmaxf(mx0, __shfl_xor_sync(0xffffffffu, mx0, 2));
            mx1 = fmaxf(mx1, __shfl_xor_sync(0xffffffffu, mx1, 1));
            mx1 = fmaxf(mx1, __shfl_xor_sync(0xffffffffu, mx1, 2));
            float mn0 = fmaxf(m0, mx0), mn1 = fmaxf(m1, mx1);
            float c0 = __expf(m0 - mn0), c1 = __expf(m1 - mn1);
            m0 = mn0; m1 = mn1;
            l0 *= c0; l1 *= c1;
            #pragma unroll
            for (int nt = 0; nt < 8; nt++) {
                oacc[nt][0] *= c0; oacc[nt][1] *= c0;
                oacc[nt][2] *= c1; oacc[nt][3] *= c1;
            }
            #pragma unroll
            for (int nt = 0; nt < 8; nt++) {
                float p0 = __expf(sacc[nt][0] - m0);
                float p1 = __expf(sacc[nt][1] - m0);
                float p2 = __expf(sacc[nt][2] - m1);
                float p3 = __expf(sacc[nt][3] - m1);
                l0 += p0 + p1; l1 += p2 + p3;
                sacc[nt][0] = p0; sacc[nt][1] = p1; sacc[nt][2] = p2; sacc[nt][3] = p3;
            }
            int g = lane >> 3, lr = lane & 7;
            #pragma unroll
            for (int kp = 0; kp < 4; kp++) {
                int t0 = kp * 2, t1 = t0 + 1;
                uint32_t pah[4], pal[4];
                pah[0] = pack_hi(sacc[t0][0], sacc[t0][1]);
                pah[1] = pack_hi(sacc[t0][2], sacc[t0][3]);
                pah[2] = pack_hi(sacc[t1][0], sacc[t1][1]);
                pah[3] = pack_hi(sacc[t1][2], sacc[t1][3]);
                pal[0] = pack_lo(sacc[t0][0], sacc[t0][1]);
                pal[1] = pack_lo(sacc[t0][2], sacc[t0][3]);
                pal[2] = pack_lo(sacc[t1][0], sacc[t1][1]);
                pal[3] = pack_lo(sacc[t1][2], sacc[t1][3]);
                #pragma unroll
                for (int nd2 = 0; nd2 < 4; nd2++) {
                    uint32_t bVh[4], bVl[4];
                    uint32_t o = swz128((uint32_t)((kp * 16 + (g & 1) * 8 + lr) * 128
                                                   + nd2 * 32 + (g >> 1) * 16));
                    LDSM4T(bVh, base + 16384 + o);
                    LDSM4T(bVl, base + 24576 + o);
                    #pragma unroll
                    for (int u = 0; u < 2; u++) {
                        int nt = nd2 * 2 + u;
                        MMA(oacc[nt], pah, bVh[u * 2], bVh[u * 2 + 1]);
                        MMA(oacc[nt], pah, bVl[u * 2], bVl[u * 2 + 1]);
                        MMA(oacc[nt], pal, bVh[u * 2], bVh[u * 2 + 1]);
                    }
                }
            }
        }
        __syncthreads();
        if (t + 2 < numT) loadKV(t & 1, (t + 2) * 64);
    }

    l0 += __shfl_xor_sync(0xffffffffu, l0, 1);
    l0 += __shfl_xor_sync(0xffffffffu, l0, 2);
    l1 += __shfl_xor_sync(0xffffffffu, l1, 1);
    l1 += __shfl_xor_sync(0xffffffffu, l1, 2);
    float i0 = 1.0f / l0, i1 = 1.0f / l1;
    long long gr0 = (rowOff + row0) * (long long)Dm + h * 64 + (lane & 3) * 2;
    long long gr1 = (rowOff + row1) * (long long)Dm + h * 64 + (lane & 3) * 2;
    #pragma unroll
    for (int nt = 0; nt < 8; nt++) {
        float a0 = oacc[nt][0] * i0, a1 = oacc[nt][1] * i0;
        float a2 = oacc[nt][2] * i1, a3 = oacc[nt][3] * i1;
        *(uint32_t*)&outHi[gr0 + nt * 8] = pack_hi(a0, a1);
        *(uint32_t*)&outLo[gr0 + nt * 8] = pack_lo(a0, a1);
        *(uint32_t*)&outHi[gr1 + nt * 8] = pack_hi(a2, a3);
        *(uint32_t*)&outLo[gr1 + nt * 8] = pack_lo(a2, a3);
    }
}

// ---------------------------------------------------------------------------
extern "C" void kernel_launch(void* const* d_in, const int* in_sizes, int n_in,
                              void* d_out, int out_size)
{
    const int*   tokens  = (const int*)  d_in[0];
    const float* tok_emb = (const float*)d_in[1];
    const float* pe      = (const float*)d_in[2];
    const float* ln1_s   = (const float*)d_in[3];
    const float* ln1_b   = (const float*)d_in[4];
    const float* w_qkv   = (const float*)d_in[5];
    const float* b_qkv   = (const float*)d_in[6];
    const float* w_o     = (const float*)d_in[7];
    const float* b_o     = (const float*)d_in[8];
    const float* ln2_s   = (const float*)d_in[9];
    const float* ln2_b   = (const float*)d_in[10];
    const float* w1      = (const float*)d_in[11];
    const float* b1      = (const float*)d_in[12];
    const float* w2      = (const float*)d_in[13];
    const float* b2      = (const float*)d_in[14];
    const float* lnf_s   = (const float*)d_in[15];
    const float* lnf_b   = (const float*)d_in[16];
    const float* head_w  = (const float*)d_in[17];
    const float* head_b  = (const float*)d_in[18];
    float* out = (float*)d_out;

    float* x;
    __nv_bfloat16 *aHi, *aLo, *bHi, *bLo, *qkvTh, *qkvTl, *woTh, *woTl,
                  *w1Th, *w1Tl, *w2Th, *w2Tl, *hdTh, *hdTl;
    cudaGetSymbolAddress((void**)&x,    g_x);
    cudaGetSymbolAddress((void**)&aHi,  g_aHi);
    cudaGetSymbolAddress((void**)&aLo,  g_aLo);
    cudaGetSymbolAddress((void**)&bHi,  g_bHi);
    cudaGetSymbolAddress((void**)&bLo,  g_bLo);
    cudaGetSymbolAddress((void**)&qkvTh, g_qkvT_hi);
    cudaGetSymbolAddress((void**)&qkvTl, g_qkvT_lo);
    cudaGetSymbolAddress((void**)&woTh,  g_woT_hi);
    cudaGetSymbolAddress((void**)&woTl,  g_woT_lo);
    cudaGetSymbolAddress((void**)&w1Th,  g_w1T_hi);
    cudaGetSymbolAddress((void**)&w1Tl,  g_w1T_lo);
    cudaGetSymbolAddress((void**)&w2Th,  g_w2T_hi);
    cudaGetSymbolAddress((void**)&w2Tl,  g_w2T_lo);
    cudaGetSymbolAddress((void**)&hdTh,  g_hdT_hi);
    cudaGetSymbolAddress((void**)&hdTl,  g_hdT_lo);

    cudaFuncSetAttribute(gemm_mma, cudaFuncAttributeMaxDynamicSharedMemorySize, 98304);
    cudaFuncSetAttribute(attn_mma, cudaFuncAttributeMaxDynamicSharedMemorySize, 98304);
    const int SMEM = 98304;
    dim3 tb(256);

    embed_kernel<<<ROWS, 128>>>(tokens, tok_emb, pe, x);                               // 1
    wsplit_kernel<<<dim3(1536/32, 512/32), tb>>>(w_qkv, qkvTh, qkvTl, 512, 1536);      // 2
    ln_kernel<<<ROWS, 128>>>(x, ln1_s, ln1_b, aHi, aLo);                               // 3

    for (int l = 0; l < Lq; l++) {
        if (l > 0) {
            wsplit_kernel<<<dim3(1536/32, 512/32), tb>>>(w_qkv + (long long)l*512*1536, qkvTh + (long long)l*1536*512, qkvTl + (long long)l*1536*512, 512, 1536);
            ln_kernel<<<ROWS, 128>>>(x, ln1_s + l * Dm, ln1_b + l * Dm, aHi, aLo);
        }
        gemm_mma<<<dim3(1536/128, 32), 512, SMEM>>>(aHi, aLo,                          // #4 at l=0 (profiled)
            qkvTh + (long long)l*1536*512, qkvTl + (long long)l*1536*512,
            b_qkv + l*1536, nullptr, nullptr, bHi, bLo, 1536, 512, 3);
        attn_mma<<<dim3(Sq/128, Hh, Bq), 256, SMEM>>>(bHi, bLo, aHi, aLo);
        wsplit_kernel<<<dim3(512/32, 512/32),  tb>>>(w_o + (long long)l*512*512,  woTh + (long long)l*512*512,  woTl + (long long)l*512*512,  512, 512);
        wsplit_kernel<<<dim3(2048/32, 512/32), tb>>>(w1  + (long long)l*512*2048, w1Th + (long long)l*2048*512, w1Tl + (long long)l*2048*512, 512, 2048);
        wsplit_kernel<<<dim3(512/32, 2048/32), tb>>>(w2  + (long long)l*2048*512, w2Th + (long long)l*512*2048, w2Tl + (long long)l*512*2048, 2048, 512);
        gemm_mma<<<dim3(512/128, 32), 512, SMEM>>>(aHi, aLo,
            woTh + (long long)l*512*512, woTl + (long long)l*512*512,
            b_o + l*512, x, x, nullptr, nullptr, 512, 512, 1);
        ln_kernel<<<ROWS, 128>>>(x, ln2_s + l * Dm, ln2_b + l * Dm, aHi, aLo);
        gemm_mma<<<dim3(2048/128, 32), 512, SMEM>>>(aHi, aLo,
            w1Th + (long long)l*2048*512, w1Tl + (long long)l*2048*512,
            b1 + l*2048, nullptr, nullptr, bHi, bLo, 2048, 512, 2);
        gemm_mma<<<dim3(512/128, 32), 512, SMEM>>>(bHi, bLo,
            w2Th + (long long)l*512*2048, w2Tl + (long long)l*512*2048,
            b2 + l*512, x, x, nullptr, nullptr, 512, 2048, 1);
    }
    wsplit_kernel<<<dim3(32000/32, 512/32), tb>>>(head_w, hdTh, hdTl, 512, 32000);
    ln_kernel<<<ROWS, 128>>>(x, lnf_s, lnf_b, aHi, aLo);
    gemm_mma<<<dim3(32000/128, 32), 512, SMEM>>>(aHi, aLo, hdTh, hdTl,
        head_b, nullptr, out, nullptr, nullptr, 32000, 512, 0);
}